// round 3
// baseline (speedup 1.0000x reference)
#include <cuda_runtime.h>
#include <stdint.h>

#define N_NODES_MAX 50000
#define E_MAX 800000
#define D 128

// Scratch (__device__ globals; no allocation allowed)
__device__ int   g_cnt[N_NODES_MAX];      // in-degree (excl. self loop)
__device__ int   g_rowptr[N_NODES_MAX];   // CSR row start
__device__ int   g_woff[N_NODES_MAX];     // fill cursors
__device__ int   g_es[E_MAX];             // src indices sorted by dst
__device__ float g_inv[N_NODES_MAX];
__device__ float g_XW[(size_t)N_NODES_MAX * D];  // (X@W) * inv[row]  (pre-scaled)

// ---------------------------------------------------------------------------
// 1) zero the histogram
// ---------------------------------------------------------------------------
__global__ void k_zero(int n) {
    int i = blockIdx.x * blockDim.x + threadIdx.x;
    if (i < n) g_cnt[i] = 0;
}

// ---------------------------------------------------------------------------
// 2) in-degree histogram over edge_dst (int atomics)
// ---------------------------------------------------------------------------
__global__ void k_deg(const int* __restrict__ dst, int E) {
    int i = blockIdx.x * blockDim.x + threadIdx.x;
    if (i < E) atomicAdd(&g_cnt[dst[i]], 1);
}

// ---------------------------------------------------------------------------
// 3) single-block scan: rowptr = exclusive_prefix(cnt); woff = rowptr;
//    inv = rsqrt(cnt + 1)
// ---------------------------------------------------------------------------
#define SCAN_T 1024
__global__ void k_scan(int n) {
    __shared__ int part[SCAN_T];
    int tid = threadIdx.x;
    int chunk = (n + SCAN_T - 1) / SCAN_T;
    int s0 = tid * chunk;
    int s1 = min(s0 + chunk, n);

    int s = 0;
    for (int i = s0; i < s1; i++) s += g_cnt[i];
    part[tid] = s;
    __syncthreads();

    for (int off = 1; off < SCAN_T; off <<= 1) {
        int v = part[tid];
        int add = (tid >= off) ? part[tid - off] : 0;
        __syncthreads();
        part[tid] = v + add;
        __syncthreads();
    }

    int run = (tid > 0) ? part[tid - 1] : 0;
    for (int i = s0; i < s1; i++) {
        int c = g_cnt[i];
        g_rowptr[i] = run;
        g_woff[i]   = run;
        run += c;
        g_inv[i] = rsqrtf((float)c + 1.0f);
    }
}

// ---------------------------------------------------------------------------
// 4) CSR fill
// ---------------------------------------------------------------------------
__global__ void k_fill(const int* __restrict__ src, const int* __restrict__ dst, int E) {
    int i = blockIdx.x * blockDim.x + threadIdx.x;
    if (i < E) {
        int d = dst[i];
        int pos = atomicAdd(&g_woff[d], 1);
        g_es[pos] = src[i];
    }
}

// ---------------------------------------------------------------------------
// 5) GEMM: g_XW[r] = (X @ W)[r] * inv[r]
//    Block tile 128x128, 256 threads, 8x8 register blocking.
//    W resident in smem row-major [k][c]; X tile stored TRANSPOSED [k][r]
//    so both operand fetches are LDS.128 (4 per 64 FMAs).
// ---------------------------------------------------------------------------
#define GBM 128
#define XT_LD 132   // padded (132 = 4*33: float4-aligned rows, skewed banks)

__global__ __launch_bounds__(256) void k_gemm(const float* __restrict__ X,
                                              const float* __restrict__ W, int n) {
    extern __shared__ float sm[];
    float* Ws = sm;                   // [128][128]
    float* Xt = sm + D * D;           // [K=128][GBM] transposed, ld=XT_LD

    const int tid = threadIdx.x;
    const int row0 = blockIdx.x * GBM;

    // load W: 4096 float4
    {
        float4* dsm = (float4*)Ws;
        const float4* srcp = (const float4*)W;
        for (int i = tid; i < (D * D) / 4; i += 256) dsm[i] = srcp[i];
    }
    // load X tile transposed: X[row][k] -> Xt[k][row]
    for (int i = tid; i < GBM * (D / 4); i += 256) {
        int r = i >> 5;               // 0..127 (tile row)
        int c4 = (i & 31) * 4;        // k base
        float4 v = make_float4(0.f, 0.f, 0.f, 0.f);
        int gr = row0 + r;
        if (gr < n) v = *(const float4*)(X + (size_t)gr * D + c4);
        Xt[(c4 + 0) * XT_LD + r] = v.x;
        Xt[(c4 + 1) * XT_LD + r] = v.y;
        Xt[(c4 + 2) * XT_LD + r] = v.z;
        Xt[(c4 + 3) * XT_LD + r] = v.w;
    }
    __syncthreads();

    const int tx = tid & 15;          // 16 col groups
    const int ty = tid >> 4;          // 16 row groups
    const int c0 = tx * 8;
    const int r0 = ty * 8;

    float acc[8][8];
#pragma unroll
    for (int i = 0; i < 8; i++)
#pragma unroll
        for (int j = 0; j < 8; j++) acc[i][j] = 0.f;

#pragma unroll 4
    for (int k = 0; k < D; k++) {
        float4 xa = *(const float4*)&Xt[k * XT_LD + r0];
        float4 xb = *(const float4*)&Xt[k * XT_LD + r0 + 4];
        float4 wa = *(const float4*)&Ws[k * D + c0];
        float4 wb = *(const float4*)&Ws[k * D + c0 + 4];
        const float xv[8] = {xa.x, xa.y, xa.z, xa.w, xb.x, xb.y, xb.z, xb.w};
        const float wv[8] = {wa.x, wa.y, wa.z, wa.w, wb.x, wb.y, wb.z, wb.w};
#pragma unroll
        for (int i = 0; i < 8; i++)
#pragma unroll
            for (int j = 0; j < 8; j++)
                acc[i][j] = fmaf(xv[i], wv[j], acc[i][j]);
    }

#pragma unroll
    for (int i = 0; i < 8; i++) {
        int r = row0 + r0 + i;
        if (r >= n) continue;
        float s = g_inv[r];
        float4 a = make_float4(acc[i][0] * s, acc[i][1] * s, acc[i][2] * s, acc[i][3] * s);
        float4 b = make_float4(acc[i][4] * s, acc[i][5] * s, acc[i][6] * s, acc[i][7] * s);
        *(float4*)&g_XW[(size_t)r * D + c0]     = a;
        *(float4*)&g_XW[(size_t)r * D + c0 + 4] = b;
    }
}

// ---------------------------------------------------------------------------
// 6) aggregation: one warp per node, zero atomics, 4-deep gather MLP.
//    out[i] = inv[i] * ( g_XW[i] + sum_{e in row(i)} g_XW[src_e] )
// ---------------------------------------------------------------------------
__global__ void k_agg(float* __restrict__ out, int n) {
    int node = (int)((blockIdx.x * (size_t)blockDim.x + threadIdx.x) >> 5);
    int lane = threadIdx.x & 31;
    if (node >= n) return;

    const float4* base = (const float4*)g_XW;
    int beg = g_rowptr[node];
    int cnt = g_cnt[node];

    float4 acc = base[(size_t)node * 32 + lane];  // self term (pre-scaled)

    int j = 0;
    for (; j + 3 < cnt; j += 4) {
        int s0 = __ldg(&g_es[beg + j + 0]);
        int s1 = __ldg(&g_es[beg + j + 1]);
        int s2 = __ldg(&g_es[beg + j + 2]);
        int s3 = __ldg(&g_es[beg + j + 3]);
        float4 v0 = base[(size_t)s0 * 32 + lane];
        float4 v1 = base[(size_t)s1 * 32 + lane];
        float4 v2 = base[(size_t)s2 * 32 + lane];
        float4 v3 = base[(size_t)s3 * 32 + lane];
        acc.x += (v0.x + v1.x) + (v2.x + v3.x);
        acc.y += (v0.y + v1.y) + (v2.y + v3.y);
        acc.z += (v0.z + v1.z) + (v2.z + v3.z);
        acc.w += (v0.w + v1.w) + (v2.w + v3.w);
    }
    for (; j < cnt; j++) {
        int s0 = __ldg(&g_es[beg + j]);
        float4 v0 = base[(size_t)s0 * 32 + lane];
        acc.x += v0.x; acc.y += v0.y; acc.z += v0.z; acc.w += v0.w;
    }

    float inv = g_inv[node];
    float4 o = make_float4(acc.x * inv, acc.y * inv, acc.z * inv, acc.w * inv);
    ((float4*)out)[(size_t)node * 32 + lane] = o;
}

// ---------------------------------------------------------------------------
extern "C" void kernel_launch(void* const* d_in, const int* in_sizes, int n_in,
                              void* d_out, int out_size) {
    const float* X = (const float*)d_in[0];
    const float* W = (const float*)d_in[1];
    const int* esrc = (const int*)d_in[2];
    const int* edst = (const int*)d_in[3];
    float* out = (float*)d_out;

    int n = in_sizes[0] / D;     // 50000
    int E = in_sizes[2];         // 800000

    static int smem_set = 0;
    int smem_bytes = D * D * sizeof(float) + D * XT_LD * sizeof(float);
    if (!smem_set) {
        cudaFuncSetAttribute(k_gemm, cudaFuncAttributeMaxDynamicSharedMemorySize, smem_bytes);
        smem_set = 1;
    }

    k_zero<<<(n + 255) / 256, 256>>>(n);
    k_deg<<<(E + 255) / 256, 256>>>(edst, E);
    k_scan<<<1, SCAN_T>>>(n);
    k_fill<<<(E + 255) / 256, 256>>>(esrc, edst, E);
    k_gemm<<<(n + GBM - 1) / GBM, 256, smem_bytes>>>(X, W, n);

    int warps_per_block = 256 / 32;
    int nblk = (n + warps_per_block - 1) / warps_per_block;
    k_agg<<<nblk, 256>>>(out, n);
}

// round 4
// speedup vs baseline: 1.0239x; 1.0239x over previous
#include <cuda_runtime.h>
#include <stdint.h>

#define N_NODES_MAX 50000
#define E_MAX 800000
#define D 128

// Scratch (__device__ globals; no allocation allowed)
__device__ int   g_cnt[N_NODES_MAX];      // in-degree (excl. self loop)
__device__ int   g_rowptr[N_NODES_MAX];   // CSR row start
__device__ int   g_woff[N_NODES_MAX];     // fill cursors
__device__ int   g_es[E_MAX];             // src indices sorted by dst
__device__ float g_inv[N_NODES_MAX];
__device__ float g_XW[(size_t)N_NODES_MAX * D];  // X @ W (UNscaled)

// ---------------------------------------------------------------------------
// 1) zero the histogram
// ---------------------------------------------------------------------------
__global__ void k_zero(int n) {
    int i = blockIdx.x * blockDim.x + threadIdx.x;
    if (i < n) g_cnt[i] = 0;
}

// ---------------------------------------------------------------------------
// 2) in-degree histogram over edge_dst (int atomics)
// ---------------------------------------------------------------------------
__global__ void k_deg(const int* __restrict__ dst, int E) {
    int i = blockIdx.x * blockDim.x + threadIdx.x;
    if (i < E) atomicAdd(&g_cnt[dst[i]], 1);
}

// ---------------------------------------------------------------------------
// 3) single-block scan: rowptr = exclusive_prefix(cnt); woff = rowptr;
//    inv = rsqrt(cnt + 1)
// ---------------------------------------------------------------------------
#define SCAN_T 1024
__global__ void k_scan(int n) {
    __shared__ int part[SCAN_T];
    int tid = threadIdx.x;
    int chunk = (n + SCAN_T - 1) / SCAN_T;
    int s0 = tid * chunk;
    int s1 = min(s0 + chunk, n);

    int s = 0;
    for (int i = s0; i < s1; i++) s += g_cnt[i];
    part[tid] = s;
    __syncthreads();

    for (int off = 1; off < SCAN_T; off <<= 1) {
        int v = part[tid];
        int add = (tid >= off) ? part[tid - off] : 0;
        __syncthreads();
        part[tid] = v + add;
        __syncthreads();
    }

    int run = (tid > 0) ? part[tid - 1] : 0;
    for (int i = s0; i < s1; i++) {
        int c = g_cnt[i];
        g_rowptr[i] = run;
        g_woff[i]   = run;
        run += c;
        g_inv[i] = rsqrtf((float)c + 1.0f);
    }
}

// ---------------------------------------------------------------------------
// 4) CSR fill
// ---------------------------------------------------------------------------
__global__ void k_fill(const int* __restrict__ src, const int* __restrict__ dst, int E) {
    int i = blockIdx.x * blockDim.x + threadIdx.x;
    if (i < E) {
        int d = dst[i];
        int pos = atomicAdd(&g_woff[d], 1);
        g_es[pos] = src[i];
    }
}

// ---------------------------------------------------------------------------
// 5) GEMM: g_XW = X @ W (no scaling -> no dependency on the CSR chain,
//    so it runs concurrently with zero/deg/scan/fill on another stream).
//    Block tile 128x128, 256 threads, 8x8 register blocking, both operands
//    fetched as LDS.128 (X panel stored transposed).
// ---------------------------------------------------------------------------
#define GBM 128
#define XT_LD 132   // padded (4-float4-aligned rows, skewed banks)

__global__ __launch_bounds__(256) void k_gemm(const float* __restrict__ X,
                                              const float* __restrict__ W, int n) {
    extern __shared__ float sm[];
    float* Ws = sm;                   // [128][128]
    float* Xt = sm + D * D;           // [K=128][GBM] transposed, ld=XT_LD

    const int tid = threadIdx.x;
    const int row0 = blockIdx.x * GBM;

    {
        float4* dsm = (float4*)Ws;
        const float4* srcp = (const float4*)W;
        for (int i = tid; i < (D * D) / 4; i += 256) dsm[i] = srcp[i];
    }
    for (int i = tid; i < GBM * (D / 4); i += 256) {
        int r = i >> 5;
        int c4 = (i & 31) * 4;
        float4 v = make_float4(0.f, 0.f, 0.f, 0.f);
        int gr = row0 + r;
        if (gr < n) v = *(const float4*)(X + (size_t)gr * D + c4);
        Xt[(c4 + 0) * XT_LD + r] = v.x;
        Xt[(c4 + 1) * XT_LD + r] = v.y;
        Xt[(c4 + 2) * XT_LD + r] = v.z;
        Xt[(c4 + 3) * XT_LD + r] = v.w;
    }
    __syncthreads();

    const int tx = tid & 15;
    const int ty = tid >> 4;
    const int c0 = tx * 8;
    const int r0 = ty * 8;

    float acc[8][8];
#pragma unroll
    for (int i = 0; i < 8; i++)
#pragma unroll
        for (int j = 0; j < 8; j++) acc[i][j] = 0.f;

#pragma unroll 4
    for (int k = 0; k < D; k++) {
        float4 xa = *(const float4*)&Xt[k * XT_LD + r0];
        float4 xb = *(const float4*)&Xt[k * XT_LD + r0 + 4];
        float4 wa = *(const float4*)&Ws[k * D + c0];
        float4 wb = *(const float4*)&Ws[k * D + c0 + 4];
        const float xv[8] = {xa.x, xa.y, xa.z, xa.w, xb.x, xb.y, xb.z, xb.w};
        const float wv[8] = {wa.x, wa.y, wa.z, wa.w, wb.x, wb.y, wb.z, wb.w};
#pragma unroll
        for (int i = 0; i < 8; i++)
#pragma unroll
            for (int j = 0; j < 8; j++)
                acc[i][j] = fmaf(xv[i], wv[j], acc[i][j]);
    }

#pragma unroll
    for (int i = 0; i < 8; i++) {
        int r = row0 + r0 + i;
        if (r >= n) continue;
        *(float4*)&g_XW[(size_t)r * D + c0]     =
            make_float4(acc[i][0], acc[i][1], acc[i][2], acc[i][3]);
        *(float4*)&g_XW[(size_t)r * D + c0 + 4] =
            make_float4(acc[i][4], acc[i][5], acc[i][6], acc[i][7]);
    }
}

// ---------------------------------------------------------------------------
// 6) aggregation: one warp per node, zero atomics, warp-staged indices.
//    out[i] = inv[i] * ( inv[i]*XW[i] + sum_e inv[src_e]*XW[src_e] )
//    Lane l loads index l of the chunk (coalesced), shfl broadcasts drive
//    up to 32 independent float4 row-gathers in flight per warp.
// ---------------------------------------------------------------------------
__global__ void k_agg(float* __restrict__ out, int n) {
    int node = (int)((blockIdx.x * (size_t)blockDim.x + threadIdx.x) >> 5);
    int lane = threadIdx.x & 31;
    if (node >= n) return;

    const float4* base = (const float4*)g_XW;
    int beg = g_rowptr[node];
    int cnt = g_cnt[node];
    float inv_i = g_inv[node];

    float4 sv = base[(size_t)node * 32 + lane];
    float4 acc = make_float4(sv.x * inv_i, sv.y * inv_i, sv.z * inv_i, sv.w * inv_i);

    for (int c0 = 0; c0 < cnt; c0 += 32) {
        int m = min(32, cnt - c0);
        int idx = 0;
        float wsrc = 0.f;
        if (lane < m) {
            idx = __ldg(&g_es[beg + c0 + lane]);   // coalesced
            wsrc = __ldg(&g_inv[idx]);
        }
#pragma unroll 4
        for (int k = 0; k < m; k++) {
            int s = __shfl_sync(0xffffffffu, idx, k);
            float ws = __shfl_sync(0xffffffffu, wsrc, k);
            float4 v = base[(size_t)s * 32 + lane];
            acc.x = fmaf(v.x, ws, acc.x);
            acc.y = fmaf(v.y, ws, acc.y);
            acc.z = fmaf(v.z, ws, acc.z);
            acc.w = fmaf(v.w, ws, acc.w);
        }
    }

    float4 o = make_float4(acc.x * inv_i, acc.y * inv_i, acc.z * inv_i, acc.w * inv_i);
    ((float4*)out)[(size_t)node * 32 + lane] = o;
}

// ---------------------------------------------------------------------------
extern "C" void kernel_launch(void* const* d_in, const int* in_sizes, int n_in,
                              void* d_out, int out_size) {
    const float* X = (const float*)d_in[0];
    const float* W = (const float*)d_in[1];
    const int* esrc = (const int*)d_in[2];
    const int* edst = (const int*)d_in[3];
    float* out = (float*)d_out;

    int n = in_sizes[0] / D;     // 50000
    int E = in_sizes[2];         // 800000

    static cudaStream_t s_gemm = nullptr;
    static cudaEvent_t ev_fork = nullptr, ev_join = nullptr;
    static int smem_bytes = 0;
    if (!s_gemm) {
        // First call is the uncaptured correctness run: safe to create
        // streams/events and set attributes here. Reused on capture calls.
        smem_bytes = D * D * sizeof(float) + D * XT_LD * sizeof(float);
        cudaFuncSetAttribute(k_gemm, cudaFuncAttributeMaxDynamicSharedMemorySize, smem_bytes);
        cudaStreamCreateWithFlags(&s_gemm, cudaStreamNonBlocking);
        cudaEventCreateWithFlags(&ev_fork, cudaEventDisableTiming);
        cudaEventCreateWithFlags(&ev_join, cudaEventDisableTiming);
    }

    // Fork: GEMM (independent of CSR build) on s_gemm
    cudaEventRecord(ev_fork, 0);
    cudaStreamWaitEvent(s_gemm, ev_fork, 0);
    k_gemm<<<(n + GBM - 1) / GBM, 256, smem_bytes, s_gemm>>>(X, W, n);
    cudaEventRecord(ev_join, s_gemm);

    // CSR build chain on the main (capture) stream, concurrent with GEMM
    k_zero<<<(n + 255) / 256, 256>>>(n);
    k_deg<<<(E + 255) / 256, 256>>>(edst, E);
    k_scan<<<1, SCAN_T>>>(n);
    k_fill<<<(E + 255) / 256, 256>>>(esrc, edst, E);

    // Join, then aggregate
    cudaStreamWaitEvent(0, ev_join, 0);
    int warps_per_block = 256 / 32;
    int nblk = (n + warps_per_block - 1) / warps_per_block;
    k_agg<<<nblk, 256>>>(out, n);
}

// round 5
// speedup vs baseline: 1.8365x; 1.7936x over previous
#include <cuda_runtime.h>
#include <stdint.h>

#define N_NODES_MAX 50000
#define E_MAX 800000
#define D 128

#define SCAN_CHUNK 1024                      // elements per block in scan
#define SCAN_NBLK ((N_NODES_MAX + SCAN_CHUNK - 1) / SCAN_CHUNK)  // 49

// Scratch (__device__ globals; no allocation allowed)
__device__ int   g_cnt[N_NODES_MAX];      // in-degree (excl. self loop)
__device__ int   g_rowptr[N_NODES_MAX];   // CSR row start
__device__ int   g_woff[N_NODES_MAX];     // fill cursors
__device__ int   g_es[E_MAX];             // src indices sorted by dst
__device__ float g_inv[N_NODES_MAX];
__device__ int   g_bsum[SCAN_NBLK];       // per-block sums
__device__ int   g_boff[SCAN_NBLK];       // exclusive block offsets
__device__ float g_XW[(size_t)N_NODES_MAX * D];  // X @ W (UNscaled)

// ---------------------------------------------------------------------------
// 1) zero the histogram
// ---------------------------------------------------------------------------
__global__ void k_zero(int n) {
    int i = blockIdx.x * blockDim.x + threadIdx.x;
    if (i < n) g_cnt[i] = 0;
}

// ---------------------------------------------------------------------------
// 2) in-degree histogram over edge_dst (int atomics)
// ---------------------------------------------------------------------------
__global__ void k_deg(const int* __restrict__ dst, int E) {
    int i = blockIdx.x * blockDim.x + threadIdx.x;
    if (i < E) atomicAdd(&g_cnt[dst[i]], 1);
}

// ---------------------------------------------------------------------------
// 3a) per-block sums: block b reduces g_cnt[b*1024 .. b*1024+1023]
// ---------------------------------------------------------------------------
__global__ void k_bsum(int n) {
    __shared__ int wsum[8];
    int tid = threadIdx.x;
    int base = blockIdx.x * SCAN_CHUNK + tid * 4;
    int s = 0;
#pragma unroll
    for (int j = 0; j < 4; j++) s += (base + j < n) ? g_cnt[base + j] : 0;
    // warp reduce
#pragma unroll
    for (int off = 16; off > 0; off >>= 1) s += __shfl_down_sync(0xffffffffu, s, off);
    if ((tid & 31) == 0) wsum[tid >> 5] = s;
    __syncthreads();
    if (tid == 0) {
        int t = 0;
#pragma unroll
        for (int w = 0; w < 8; w++) t += wsum[w];
        g_bsum[blockIdx.x] = t;
    }
}

// ---------------------------------------------------------------------------
// 3b) tiny scan of the block sums (49 values, one warp-ish block)
// ---------------------------------------------------------------------------
__global__ void k_bscan() {
    __shared__ int sh[SCAN_NBLK];
    int tid = threadIdx.x;
    if (tid < SCAN_NBLK) sh[tid] = g_bsum[tid];
    __syncthreads();
    if (tid == 0) {
        int run = 0;
        for (int i = 0; i < SCAN_NBLK; i++) { int c = sh[i]; sh[i] = run; run += c; }
    }
    __syncthreads();
    if (tid < SCAN_NBLK) g_boff[tid] = sh[tid];
}

// ---------------------------------------------------------------------------
// 3c) in-block exclusive scan + apply: rowptr/woff/inv
// ---------------------------------------------------------------------------
__global__ void k_scan_apply(int n) {
    __shared__ int wsum[8];
    int tid = threadIdx.x;
    int lane = tid & 31, wid = tid >> 5;
    int base = blockIdx.x * SCAN_CHUNK + tid * 4;

    int c[4];
#pragma unroll
    for (int j = 0; j < 4; j++) c[j] = (base + j < n) ? g_cnt[base + j] : 0;
    int s = c[0] + c[1] + c[2] + c[3];

    // warp inclusive scan of s
    int v = s;
#pragma unroll
    for (int off = 1; off < 32; off <<= 1) {
        int t = __shfl_up_sync(0xffffffffu, v, off);
        if (lane >= off) v += t;
    }
    if (lane == 31) wsum[wid] = v;
    __syncthreads();
    if (tid == 0) {
        int run = 0;
#pragma unroll
        for (int w = 0; w < 8; w++) { int t = wsum[w]; wsum[w] = run; run += t; }
    }
    __syncthreads();

    int run = (v - s) + wsum[wid] + g_boff[blockIdx.x];  // exclusive prefix
#pragma unroll
    for (int j = 0; j < 4; j++) {
        int i = base + j;
        if (i < n) {
            g_rowptr[i] = run;
            g_woff[i]   = run;
            g_inv[i]    = rsqrtf((float)c[j] + 1.0f);
            run += c[j];
        }
    }
}

// ---------------------------------------------------------------------------
// 4) CSR fill
// ---------------------------------------------------------------------------
__global__ void k_fill(const int* __restrict__ src, const int* __restrict__ dst, int E) {
    int i = blockIdx.x * blockDim.x + threadIdx.x;
    if (i < E) {
        int d = dst[i];
        int pos = atomicAdd(&g_woff[d], 1);
        g_es[pos] = src[i];
    }
}

// ---------------------------------------------------------------------------
// 5) GEMM: g_XW = X @ W (independent of CSR chain -> forked stream)
//    Block tile 128x128, 256 threads, 8x8 register blocking.
// ---------------------------------------------------------------------------
#define GBM 128
#define XT_LD 132

__global__ __launch_bounds__(256) void k_gemm(const float* __restrict__ X,
                                              const float* __restrict__ W, int n) {
    extern __shared__ float sm[];
    float* Ws = sm;                   // [128][128]
    float* Xt = sm + D * D;           // [K=128][GBM] transposed, ld=XT_LD

    const int tid = threadIdx.x;
    const int row0 = blockIdx.x * GBM;

    {
        float4* dsm = (float4*)Ws;
        const float4* srcp = (const float4*)W;
        for (int i = tid; i < (D * D) / 4; i += 256) dsm[i] = srcp[i];
    }
    for (int i = tid; i < GBM * (D / 4); i += 256) {
        int r = i >> 5;
        int c4 = (i & 31) * 4;
        float4 v = make_float4(0.f, 0.f, 0.f, 0.f);
        int gr = row0 + r;
        if (gr < n) v = *(const float4*)(X + (size_t)gr * D + c4);
        Xt[(c4 + 0) * XT_LD + r] = v.x;
        Xt[(c4 + 1) * XT_LD + r] = v.y;
        Xt[(c4 + 2) * XT_LD + r] = v.z;
        Xt[(c4 + 3) * XT_LD + r] = v.w;
    }
    __syncthreads();

    const int tx = tid & 15;
    const int ty = tid >> 4;
    const int c0 = tx * 8;
    const int r0 = ty * 8;

    float acc[8][8];
#pragma unroll
    for (int i = 0; i < 8; i++)
#pragma unroll
        for (int j = 0; j < 8; j++) acc[i][j] = 0.f;

#pragma unroll 4
    for (int k = 0; k < D; k++) {
        float4 xa = *(const float4*)&Xt[k * XT_LD + r0];
        float4 xb = *(const float4*)&Xt[k * XT_LD + r0 + 4];
        float4 wa = *(const float4*)&Ws[k * D + c0];
        float4 wb = *(const float4*)&Ws[k * D + c0 + 4];
        const float xv[8] = {xa.x, xa.y, xa.z, xa.w, xb.x, xb.y, xb.z, xb.w};
        const float wv[8] = {wa.x, wa.y, wa.z, wa.w, wb.x, wb.y, wb.z, wb.w};
#pragma unroll
        for (int i = 0; i < 8; i++)
#pragma unroll
            for (int j = 0; j < 8; j++)
                acc[i][j] = fmaf(xv[i], wv[j], acc[i][j]);
    }

#pragma unroll
    for (int i = 0; i < 8; i++) {
        int r = row0 + r0 + i;
        if (r >= n) continue;
        *(float4*)&g_XW[(size_t)r * D + c0]     =
            make_float4(acc[i][0], acc[i][1], acc[i][2], acc[i][3]);
        *(float4*)&g_XW[(size_t)r * D + c0 + 4] =
            make_float4(acc[i][4], acc[i][5], acc[i][6], acc[i][7]);
    }
}

// ---------------------------------------------------------------------------
// 6) aggregation: one warp per node, zero atomics, warp-staged indices.
//    out[i] = inv[i] * ( inv[i]*XW[i] + sum_e inv[src_e]*XW[src_e] )
// ---------------------------------------------------------------------------
__global__ void k_agg(float* __restrict__ out, int n) {
    int node = (int)((blockIdx.x * (size_t)blockDim.x + threadIdx.x) >> 5);
    int lane = threadIdx.x & 31;
    if (node >= n) return;

    const float4* base = (const float4*)g_XW;
    int beg = g_rowptr[node];
    int cnt = g_cnt[node];
    float inv_i = g_inv[node];

    float4 sv = base[(size_t)node * 32 + lane];
    float4 acc = make_float4(sv.x * inv_i, sv.y * inv_i, sv.z * inv_i, sv.w * inv_i);

    for (int c0 = 0; c0 < cnt; c0 += 32) {
        int m = min(32, cnt - c0);
        int idx = 0;
        float wsrc = 0.f;
        if (lane < m) {
            idx = __ldg(&g_es[beg + c0 + lane]);   // coalesced
            wsrc = __ldg(&g_inv[idx]);
        }
#pragma unroll 4
        for (int k = 0; k < m; k++) {
            int s = __shfl_sync(0xffffffffu, idx, k);
            float ws = __shfl_sync(0xffffffffu, wsrc, k);
            float4 v = base[(size_t)s * 32 + lane];
            acc.x = fmaf(v.x, ws, acc.x);
            acc.y = fmaf(v.y, ws, acc.y);
            acc.z = fmaf(v.z, ws, acc.z);
            acc.w = fmaf(v.w, ws, acc.w);
        }
    }

    float4 o = make_float4(acc.x * inv_i, acc.y * inv_i, acc.z * inv_i, acc.w * inv_i);
    ((float4*)out)[(size_t)node * 32 + lane] = o;
}

// ---------------------------------------------------------------------------
extern "C" void kernel_launch(void* const* d_in, const int* in_sizes, int n_in,
                              void* d_out, int out_size) {
    const float* X = (const float*)d_in[0];
    const float* W = (const float*)d_in[1];
    const int* esrc = (const int*)d_in[2];
    const int* edst = (const int*)d_in[3];
    float* out = (float*)d_out;

    int n = in_sizes[0] / D;     // 50000
    int E = in_sizes[2];         // 800000

    static cudaStream_t s_gemm = nullptr;
    static cudaEvent_t ev_fork = nullptr, ev_join = nullptr;
    static int smem_bytes = 0;
    if (!s_gemm) {
        smem_bytes = D * D * sizeof(float) + D * XT_LD * sizeof(float);
        cudaFuncSetAttribute(k_gemm, cudaFuncAttributeMaxDynamicSharedMemorySize, smem_bytes);
        cudaStreamCreateWithFlags(&s_gemm, cudaStreamNonBlocking);
        cudaEventCreateWithFlags(&ev_fork, cudaEventDisableTiming);
        cudaEventCreateWithFlags(&ev_join, cudaEventDisableTiming);
    }

    // Fork: GEMM (independent of CSR build) on s_gemm
    cudaEventRecord(ev_fork, 0);
    cudaStreamWaitEvent(s_gemm, ev_fork, 0);
    k_gemm<<<(n + GBM - 1) / GBM, 256, smem_bytes, s_gemm>>>(X, W, n);
    cudaEventRecord(ev_join, s_gemm);

    // CSR build chain on the main (capture) stream, concurrent with GEMM
    k_zero<<<(n + 255) / 256, 256>>>(n);
    k_deg<<<(E + 255) / 256, 256>>>(edst, E);
    k_bsum<<<SCAN_NBLK, 256>>>(n);
    k_bscan<<<1, 64>>>();
    k_scan_apply<<<SCAN_NBLK, 256>>>(n);
    k_fill<<<(E + 255) / 256, 256>>>(esrc, edst, E);

    // Join, then aggregate
    cudaStreamWaitEvent(0, ev_join, 0);
    int warps_per_block = 256 / 32;
    int nblk = (n + warps_per_block - 1) / warps_per_block;
    k_agg<<<nblk, 256>>>(out, n);
}